// round 1
// baseline (speedup 1.0000x reference)
#include <cuda_runtime.h>
#include <cuda_bf16.h>

// Problem constants
#define BATCH 4
#define SEQ   2048
#define CIN   1024
#define HID   1024

// Scratch: __device__ globals (allocation APIs are forbidden).
__device__ float g_qp[BATCH * SEQ * HID];   // 32 MB
__device__ float g_kp[BATCH * SEQ * HID];   // 32 MB
__device__ float g_vp[BATCH * SEQ * HID];   // 32 MB
__device__ float g_S [(long)BATCH * SEQ * SEQ]; // 64 MB

#define BM 128
#define BN 128
#define BK 8
#define NTHREADS 256

// ---------------------------------------------------------------------------
// NN SGEMM: C[M,N] = A[M,K] @ B[K,N], all row-major, optional batch strides
// via blockIdx.z, optional causal K-limit (K loop stops at end of this row
// block — valid because upper-triangle of P is exactly zero).
// 128x128 block tile, BK=8, 256 threads, 8x8 micro-tile per thread.
// ---------------------------------------------------------------------------
__global__ __launch_bounds__(NTHREADS)
void sgemm_nn(const float* __restrict__ A, const float* __restrict__ B,
              float* __restrict__ C, int M, int N, int K,
              long sA, long sB, long sC, int causalKlim)
{
    const int bm = blockIdx.y, bn = blockIdx.x, bz = blockIdx.z;
    A += (long)bz * sA;
    B += (long)bz * sB;
    C += (long)bz * sC;

    const int kmax = causalKlim ? min(K, (bm + 1) * BM) : K;

    __shared__ float As[BK][BM];
    __shared__ float Bs[BK][BN];

    const int tid = threadIdx.x;
    // A tile loader: 128 rows x 8 cols; one float4 per thread
    const int ar = tid >> 1;           // 0..127
    const int ac = (tid & 1) * 4;      // 0 or 4
    // B tile loader: 8 rows x 128 cols; one float4 per thread
    const int br = tid >> 5;           // 0..7
    const int bc = (tid & 31) * 4;     // 0..124
    // compute mapping: 16x16 threads, each 8x8 outputs
    const int ty = tid >> 4;           // 0..15
    const int tx = tid & 15;           // 0..15

    float acc[8][8];
#pragma unroll
    for (int i = 0; i < 8; i++)
#pragma unroll
        for (int j = 0; j < 8; j++) acc[i][j] = 0.0f;

    const float* Aptr = A + (long)(bm * BM + ar) * K + ac;
    const float* Bptr = B + (long)br * N + bn * BN + bc;

    for (int k0 = 0; k0 < kmax; k0 += BK) {
        float4 av = *(const float4*)(Aptr + k0);
        float4 bv = *(const float4*)(Bptr + (long)k0 * N);
        As[ac + 0][ar] = av.x;
        As[ac + 1][ar] = av.y;
        As[ac + 2][ar] = av.z;
        As[ac + 3][ar] = av.w;
        *(float4*)&Bs[br][bc] = bv;
        __syncthreads();

#pragma unroll
        for (int k = 0; k < BK; k++) {
            float4 a0 = *(const float4*)&As[k][ty * 8];
            float4 a1 = *(const float4*)&As[k][ty * 8 + 4];
            float4 b0 = *(const float4*)&Bs[k][tx * 8];
            float4 b1 = *(const float4*)&Bs[k][tx * 8 + 4];
            float a[8] = {a0.x, a0.y, a0.z, a0.w, a1.x, a1.y, a1.z, a1.w};
            float b[8] = {b0.x, b0.y, b0.z, b0.w, b1.x, b1.y, b1.z, b1.w};
#pragma unroll
            for (int i = 0; i < 8; i++)
#pragma unroll
                for (int j = 0; j < 8; j++)
                    acc[i][j] = fmaf(a[i], b[j], acc[i][j]);
        }
        __syncthreads();
    }

#pragma unroll
    for (int i = 0; i < 8; i++) {
        const int row = bm * BM + ty * 8 + i;
        float4* cp = (float4*)(C + (long)row * N + bn * BN + tx * 8);
        cp[0] = make_float4(acc[i][0], acc[i][1], acc[i][2], acc[i][3]);
        cp[1] = make_float4(acc[i][4], acc[i][5], acc[i][6], acc[i][7]);
    }
}

// ---------------------------------------------------------------------------
// NT SGEMM with causal block skip: C[M,N] = A[M,K] @ B[N,K]^T (both row-major
// with K contiguous). Blocks strictly above the diagonal exit immediately
// (their outputs are never read by the softmax). blockIdx.z = batch.
// ---------------------------------------------------------------------------
__global__ __launch_bounds__(NTHREADS)
void sgemm_nt_causal(const float* __restrict__ A, const float* __restrict__ B,
                     float* __restrict__ C, int M, int N, int K,
                     long sA, long sB, long sC)
{
    const int bm = blockIdx.y, bn = blockIdx.x, bz = blockIdx.z;
    if (bn > bm) return;  // fully-masked block (BM == BN)

    A += (long)bz * sA;
    B += (long)bz * sB;
    C += (long)bz * sC;

    __shared__ float As[BK][BM];
    __shared__ float Bs[BK][BN];

    const int tid = threadIdx.x;
    const int ar = tid >> 1;
    const int ac = (tid & 1) * 4;
    const int ty = tid >> 4;
    const int tx = tid & 15;

    float acc[8][8];
#pragma unroll
    for (int i = 0; i < 8; i++)
#pragma unroll
        for (int j = 0; j < 8; j++) acc[i][j] = 0.0f;

    const float* Aptr = A + (long)(bm * BM + ar) * K + ac;
    const float* Bptr = B + (long)(bn * BN + ar) * K + ac;  // same loader shape as A

    for (int k0 = 0; k0 < K; k0 += BK) {
        float4 av = *(const float4*)(Aptr + k0);
        float4 bv = *(const float4*)(Bptr + k0);
        As[ac + 0][ar] = av.x;
        As[ac + 1][ar] = av.y;
        As[ac + 2][ar] = av.z;
        As[ac + 3][ar] = av.w;
        Bs[ac + 0][ar] = bv.x;
        Bs[ac + 1][ar] = bv.y;
        Bs[ac + 2][ar] = bv.z;
        Bs[ac + 3][ar] = bv.w;
        __syncthreads();

#pragma unroll
        for (int k = 0; k < BK; k++) {
            float4 a0 = *(const float4*)&As[k][ty * 8];
            float4 a1 = *(const float4*)&As[k][ty * 8 + 4];
            float4 b0 = *(const float4*)&Bs[k][tx * 8];
            float4 b1 = *(const float4*)&Bs[k][tx * 8 + 4];
            float a[8] = {a0.x, a0.y, a0.z, a0.w, a1.x, a1.y, a1.z, a1.w};
            float b[8] = {b0.x, b0.y, b0.z, b0.w, b1.x, b1.y, b1.z, b1.w};
#pragma unroll
            for (int i = 0; i < 8; i++)
#pragma unroll
                for (int j = 0; j < 8; j++)
                    acc[i][j] = fmaf(a[i], b[j], acc[i][j]);
        }
        __syncthreads();
    }

#pragma unroll
    for (int i = 0; i < 8; i++) {
        const int row = bm * BM + ty * 8 + i;
        float4* cp = (float4*)(C + (long)row * N + bn * BN + tx * 8);
        cp[0] = make_float4(acc[i][0], acc[i][1], acc[i][2], acc[i][3]);
        cp[1] = make_float4(acc[i][4], acc[i][5], acc[i][6], acc[i][7]);
    }
}

// ---------------------------------------------------------------------------
// Causal softmax in-place on S[b, t, :]. Valid columns: [0, t]; columns
// (t, T) are set to exactly 0 so the PV GEMM needs no mask.
// One block per (t, b) row, 256 threads.
// ---------------------------------------------------------------------------
__global__ __launch_bounds__(NTHREADS)
void softmax_causal(float* __restrict__ S, int T, float scale)
{
    const int t = blockIdx.x;
    const int b = blockIdx.y;
    float* row = S + ((long)b * T + t) * T;
    const int n = t + 1;
    const int tid = threadIdx.x;

    __shared__ float red[NTHREADS];

    float m = -1e30f;
    for (int i = tid; i < n; i += NTHREADS) m = fmaxf(m, row[i] * scale);
    red[tid] = m;
    __syncthreads();
    for (int s = NTHREADS / 2; s > 0; s >>= 1) {
        if (tid < s) red[tid] = fmaxf(red[tid], red[tid + s]);
        __syncthreads();
    }
    m = red[0];
    __syncthreads();

    float sum = 0.0f;
    for (int i = tid; i < n; i += NTHREADS) sum += __expf(row[i] * scale - m);
    red[tid] = sum;
    __syncthreads();
    for (int s = NTHREADS / 2; s > 0; s >>= 1) {
        if (tid < s) red[tid] += red[tid + s];
        __syncthreads();
    }
    const float inv = 1.0f / red[0];
    __syncthreads();

    for (int i = tid; i < T; i += NTHREADS) {
        float v = (i < n) ? __expf(row[i] * scale - m) * inv : 0.0f;
        row[i] = v;
    }
}

// ---------------------------------------------------------------------------
// kernel_launch — graph-capturable: kernel launches only.
// Input order (metadata): x, k, q, v, Wk, Wq, Wv.  x and Wv are unused;
// v is (faithfully) projected with Wq.
// ---------------------------------------------------------------------------
extern "C" void kernel_launch(void* const* d_in, const int* in_sizes, int n_in,
                              void* d_out, int out_size)
{
    const float* kin = (const float*)d_in[1];
    const float* qin = (const float*)d_in[2];
    const float* vin = (const float*)d_in[3];
    const float* Wk  = (const float*)d_in[4];
    const float* Wq  = (const float*)d_in[5];
    float* out = (float*)d_out;

    float *qp, *kp, *vp, *S;
    cudaGetSymbolAddress((void**)&qp, g_qp);
    cudaGetSymbolAddress((void**)&kp, g_kp);
    cudaGetSymbolAddress((void**)&vp, g_vp);
    cudaGetSymbolAddress((void**)&S,  g_S);

    const int M  = BATCH * SEQ;      // 8192
    const float scale = 1.0f / 32.0f; // HID^-0.5

    dim3 blk(NTHREADS);

    // 1. Projections: qp = q@Wq, kp = k@Wk, vp = v@Wq
    dim3 gProj(HID / BN, M / BM, 1);
    sgemm_nn<<<gProj, blk>>>(qin, Wq, qp, M, HID, CIN, 0, 0, 0, 0);
    sgemm_nn<<<gProj, blk>>>(kin, Wk, kp, M, HID, CIN, 0, 0, 0, 0);
    sgemm_nn<<<gProj, blk>>>(vin, Wq, vp, M, HID, CIN, 0, 0, 0, 0);

    // 2. S = qp @ kp^T per batch (lower-triangle blocks only)
    dim3 gS(SEQ / BN, SEQ / BM, BATCH);
    sgemm_nt_causal<<<gS, blk>>>(qp, kp, S, SEQ, SEQ, HID,
                                 (long)SEQ * HID, (long)SEQ * HID,
                                 (long)SEQ * SEQ);

    // 3. causal softmax (scale applied inside), zeros the upper triangle
    dim3 gSm(SEQ, BATCH);
    softmax_causal<<<gSm, blk>>>(S, SEQ, scale);

    // 4. out = P @ vp per batch, K-loop limited to the causal extent
    dim3 gPV(HID / BN, SEQ / BM, BATCH);
    sgemm_nn<<<gPV, blk>>>(S, vp, out, SEQ, HID, SEQ,
                           (long)SEQ * SEQ, (long)SEQ * HID,
                           (long)SEQ * HID, 1);
}

// round 3
// speedup vs baseline: 5.5603x; 5.5603x over previous
#include <cuda_runtime.h>
#include <cstdint>

#define BATCH 4
#define SEQ   2048
#define CIN   1024
#define HID   1024

// ---------------- scratch (__device__ globals; alloc APIs forbidden) -------
__device__ float g_qp [BATCH * SEQ * HID];          // 32 MB
__device__ float g_kp [BATCH * SEQ * HID];          // 32 MB
__device__ float g_vp [BATCH * SEQ * HID];          // 32 MB
__device__ float g_vpT[BATCH * SEQ * HID];          // 32 MB  (per-batch [H][T])
__device__ float g_S  [(long)BATCH * SEQ * SEQ];    // 64 MB
__device__ float g_WqT[CIN * HID];                  // 4 MB   ([H][C])
__device__ float g_WkT[CIN * HID];                  // 4 MB

// ---------------- helpers ---------------------------------------------------
__device__ __forceinline__ uint32_t smem_u32(const void* p) {
    uint32_t r;
    asm("{ .reg .u64 t; cvta.to.shared.u64 t, %1; cvt.u32.u64 %0, t; }"
        : "=r"(r) : "l"(p));
    return r;
}
__device__ __forceinline__ void cpa16(uint32_t dst, const void* src) {
    asm volatile("cp.async.cg.shared.global [%0], [%1], 16;" :: "r"(dst), "l"(src));
}
__device__ __forceinline__ uint32_t f2tf(float x) {
    uint32_t r;
    asm("cvt.rna.tf32.f32 %0, %1;" : "=r"(r) : "f"(x));
    return r;
}
__device__ __forceinline__ void mma_tf32(float* c, const uint32_t* a, const uint32_t* b) {
    asm volatile("mma.sync.aligned.m16n8k8.row.col.f32.tf32.tf32.f32 "
                 "{%0,%1,%2,%3}, {%4,%5,%6,%7}, {%8,%9}, {%0,%1,%2,%3};"
                 : "+f"(c[0]), "+f"(c[1]), "+f"(c[2]), "+f"(c[3])
                 : "r"(a[0]), "r"(a[1]), "r"(a[2]), "r"(a[3]),
                   "r"(b[0]), "r"(b[1]));
}

// ---------------- tensor-core tf32 GEMM -------------------------------------
// C[M,N] = A[M,K] @ B[N,K]^T, all row-major K-contiguous. 128x128 CTA tile,
// BK=32, 3-stage cp.async pipeline, 8 warps (4x2), warp tile 32x64.
// mode 0: full K grid (bn,bm = blockIdx.x,y)
// mode 1: causal triangular grid over blockIdx.x in [0,136)
// mode 2: K limited to (bm+1)*128 (PV with causal-zeroed P)
#define NSTAGE      3
#define STAGE_FLTS  8192          // A 4096 + B 4096 floats (32 KB)
#define GEMM_SMEM   (NSTAGE * STAGE_FLTS * 4)   // 98304 B

__global__ __launch_bounds__(256, 1)
void gemm_mma(const float* __restrict__ A, const float* __restrict__ B,
              float* __restrict__ C, int ldA, int ldB, int ldC,
              int Kdim, int mode, long strA, long strB, long strC)
{
    extern __shared__ float sm[];
    const uint32_t sbase = smem_u32(sm);
    const int tid  = threadIdx.x;
    const int lane = tid & 31;
    const int wid  = tid >> 5;
    const int wm = (wid >> 1) * 32;   // warp row offset within tile
    const int wn = (wid & 1) * 64;    // warp col offset within tile
    const int qr = lane >> 2;         // 0..7
    const int qc = lane & 3;          // 0..3
    const int xm = qr << 2;           // smem XOR mask for fragment loads

    int bm, bn;
    if (mode == 1) {
        int idx = blockIdx.x, acc = 0; bm = 0;
        while (acc + bm + 1 <= idx) { acc += bm + 1; bm++; }
        bn = idx - acc;
    } else { bn = blockIdx.x; bm = blockIdx.y; }
    const int bz = blockIdx.z;
    A += (long)bz * strA; B += (long)bz * strB; C += (long)bz * strC;

    const int kmax = (mode == 2) ? min(Kdim, (bm + 1) * 128) : Kdim;
    const int KT = kmax >> 5;         // number of BK=32 stages (>= 4 here)

    // per-thread loader precompute: 4 float4 for A, 4 for B per stage
    const float* asrc[4]; const float* bsrc[4];
    uint32_t adst[4], bdst[4];
#pragma unroll
    for (int t = 0; t < 4; t++) {
        int e = tid + t * 256;            // 0..1023
        int row = e >> 3;                 // 0..127
        int kq  = (e & 7) * 4;            // 0,4,...,28
        uint32_t didx = (uint32_t)(row * 32 + (kq ^ ((row & 7) << 2)));
        asrc[t] = A + (long)(bm * 128 + row) * ldA + kq;
        bsrc[t] = B + (long)(bn * 128 + row) * ldB + kq;
        adst[t] = sbase + didx * 4;
        bdst[t] = sbase + (didx + 4096) * 4;
    }

    float acc[2][8][4];
#pragma unroll
    for (int mt = 0; mt < 2; mt++)
#pragma unroll
        for (int nt = 0; nt < 8; nt++)
#pragma unroll
            for (int i = 0; i < 4; i++) acc[mt][nt][i] = 0.0f;

    // prologue: stages 0 and 1
#pragma unroll
    for (int s = 0; s < 2; s++) {
        uint32_t soff = (uint32_t)(s * STAGE_FLTS * 4);
#pragma unroll
        for (int t = 0; t < 4; t++) {
            cpa16(adst[t] + soff, asrc[t] + s * 32);
            cpa16(bdst[t] + soff, bsrc[t] + s * 32);
        }
        asm volatile("cp.async.commit_group;" ::: "memory");
    }

    for (int kt = 0; kt < KT; kt++) {
        asm volatile("cp.async.wait_group 1;" ::: "memory");
        __syncthreads();

        const float* As = sm + (kt % NSTAGE) * STAGE_FLTS;
        const float* Bs = As + 4096;

#pragma unroll
        for (int ks = 0; ks < 4; ks++) {
            const int k0 = ks * 8;
            const int c0 = (k0 + qc) ^ xm;
            const int c1 = (k0 + 4 + qc) ^ xm;

            uint32_t af[2][4];
#pragma unroll
            for (int mt = 0; mt < 2; mt++) {
                int r  = wm + mt * 16 + qr;
                int r8 = r + 8;
                af[mt][0] = f2tf(As[r  * 32 + c0]);
                af[mt][1] = f2tf(As[r8 * 32 + c0]);
                af[mt][2] = f2tf(As[r  * 32 + c1]);
                af[mt][3] = f2tf(As[r8 * 32 + c1]);
            }
            uint32_t bf[8][2];
#pragma unroll
            for (int nt = 0; nt < 8; nt++) {
                int n = wn + nt * 8 + qr;
                bf[nt][0] = f2tf(Bs[n * 32 + c0]);
                bf[nt][1] = f2tf(Bs[n * 32 + c1]);
            }
#pragma unroll
            for (int mt = 0; mt < 2; mt++)
#pragma unroll
                for (int nt = 0; nt < 8; nt++)
                    mma_tf32(acc[mt][nt], af[mt], bf[nt]);
        }

        // prefetch stage kt+2 into buffer (kt+2)%3 (all warps passed the sync,
        // so stage kt-1's reads of that buffer are complete)
        int sf = kt + 2;
        if (sf < KT) {
            uint32_t soff = (uint32_t)((sf % NSTAGE) * STAGE_FLTS * 4);
#pragma unroll
            for (int t = 0; t < 4; t++) {
                cpa16(adst[t] + soff, asrc[t] + sf * 32);
                cpa16(bdst[t] + soff, bsrc[t] + sf * 32);
            }
        }
        asm volatile("cp.async.commit_group;" ::: "memory");
    }

    // epilogue: accumulators -> gmem (float2 stores, no smem)
#pragma unroll
    for (int mt = 0; mt < 2; mt++) {
        int r = bm * 128 + wm + mt * 16 + qr;
#pragma unroll
        for (int nt = 0; nt < 8; nt++) {
            int col = bn * 128 + wn + nt * 8 + 2 * qc;
            float2 v0 = make_float2(acc[mt][nt][0], acc[mt][nt][1]);
            float2 v1 = make_float2(acc[mt][nt][2], acc[mt][nt][3]);
            *(float2*)&C[(long)r * ldC + col]       = v0;
            *(float2*)&C[(long)(r + 8) * ldC + col] = v1;
        }
    }
}

// ---------------- transpose: out[c][r] = in[r][c] --------------------------
__global__ __launch_bounds__(256)
void transpose_k(const float* __restrict__ in, float* __restrict__ out,
                 int R, int C, long sIn, long sOut)
{
    __shared__ float tile[32][33];
    const int bz = blockIdx.z;
    in += (long)bz * sIn; out += (long)bz * sOut;
    const int c0 = blockIdx.x * 32, r0 = blockIdx.y * 32;
    const int tx = threadIdx.x & 31, ty = threadIdx.x >> 5;   // 32 x 8
#pragma unroll
    for (int i = 0; i < 32; i += 8)
        tile[ty + i][tx] = in[(long)(r0 + ty + i) * C + c0 + tx];
    __syncthreads();
#pragma unroll
    for (int i = 0; i < 32; i += 8)
        out[(long)(c0 + ty + i) * R + r0 + tx] = tile[tx][ty + i];
}

// ---------------- causal softmax (in-place, zeros upper triangle) ----------
#define SM_THREADS 256
__global__ __launch_bounds__(SM_THREADS)
void softmax_causal(float* __restrict__ S, int T, float scale)
{
    const int t = blockIdx.x, b = blockIdx.y;
    float* row = S + ((long)b * T + t) * T;
    const int n = t + 1;
    const int tid = threadIdx.x;
    __shared__ float red[SM_THREADS];

    float m = -1e30f;
    for (int i = tid; i < n; i += SM_THREADS) m = fmaxf(m, row[i] * scale);
    red[tid] = m; __syncthreads();
    for (int s = SM_THREADS / 2; s > 0; s >>= 1) {
        if (tid < s) red[tid] = fmaxf(red[tid], red[tid + s]);
        __syncthreads();
    }
    m = red[0]; __syncthreads();

    float sum = 0.0f;
    for (int i = tid; i < n; i += SM_THREADS) sum += __expf(row[i] * scale - m);
    red[tid] = sum; __syncthreads();
    for (int s = SM_THREADS / 2; s > 0; s >>= 1) {
        if (tid < s) red[tid] += red[tid + s];
        __syncthreads();
    }
    const float inv = 1.0f / red[0];
    __syncthreads();

    for (int i = tid; i < T; i += SM_THREADS)
        row[i] = (i < n) ? __expf(row[i] * scale - m) * inv : 0.0f;
}

// ---------------- launch ---------------------------------------------------
extern "C" void kernel_launch(void* const* d_in, const int* in_sizes, int n_in,
                              void* d_out, int out_size)
{
    const float* kin = (const float*)d_in[1];
    const float* qin = (const float*)d_in[2];
    const float* vin = (const float*)d_in[3];
    const float* Wk  = (const float*)d_in[4];
    const float* Wq  = (const float*)d_in[5];
    float* out = (float*)d_out;

    float *qp, *kp, *vp, *vpT, *S, *WqT, *WkT;
    cudaGetSymbolAddress((void**)&qp,  g_qp);
    cudaGetSymbolAddress((void**)&kp,  g_kp);
    cudaGetSymbolAddress((void**)&vp,  g_vp);
    cudaGetSymbolAddress((void**)&vpT, g_vpT);
    cudaGetSymbolAddress((void**)&S,   g_S);
    cudaGetSymbolAddress((void**)&WqT, g_WqT);
    cudaGetSymbolAddress((void**)&WkT, g_WkT);

    cudaFuncSetAttribute(gemm_mma, cudaFuncAttributeMaxDynamicSharedMemorySize, GEMM_SMEM);

    const int M = BATCH * SEQ;                 // 8192
    const float scale = 1.0f / 32.0f;          // HID^-0.5
    dim3 blk(256);

    // W transposes: WqT[h][c], WkT[h][c]
    dim3 gWT(HID / 32, CIN / 32, 1);
    transpose_k<<<gWT, blk>>>(Wq, WqT, CIN, HID, 0, 0);
    transpose_k<<<gWT, blk>>>(Wk, WkT, CIN, HID, 0, 0);

    // projections: qp = q @ WqT^T, kp = k @ WkT^T, vp = v @ WqT^T (faithful bug)
    dim3 gProj(HID / 128, M / 128, 1);
    gemm_mma<<<gProj, blk, GEMM_SMEM>>>(qin, WqT, qp, CIN, CIN, HID, CIN, 0, 0, 0, 0);
    gemm_mma<<<gProj, blk, GEMM_SMEM>>>(kin, WkT, kp, CIN, CIN, HID, CIN, 0, 0, 0, 0);
    gemm_mma<<<gProj, blk, GEMM_SMEM>>>(vin, WqT, vp, CIN, CIN, HID, CIN, 0, 0, 0, 0);

    // vpT[b][h][t] = vp[b][t][h]
    dim3 gVT(HID / 32, SEQ / 32, BATCH);
    transpose_k<<<gVT, blk>>>(vp, vpT, SEQ, HID, (long)SEQ * HID, (long)SEQ * HID);

    // S = qp @ kp^T (lower-triangle blocks only: 136 per batch)
    dim3 gS(136, 1, BATCH);
    gemm_mma<<<gS, blk, GEMM_SMEM>>>(qp, kp, S, HID, HID, SEQ, HID, 1,
                                     (long)SEQ * HID, (long)SEQ * HID, (long)SEQ * SEQ);

    // softmax (scales inside, zeros upper triangle)
    dim3 gSm(SEQ, BATCH);
    softmax_causal<<<gSm, blk>>>(S, SEQ, scale);

    // out = P @ vpT^T, K limited causally per row-block
    dim3 gPV(HID / 128, SEQ / 128, BATCH);
    gemm_mma<<<gPV, blk, GEMM_SMEM>>>(S, vpT, out, SEQ, SEQ, HID, SEQ, 2,
                                      (long)SEQ * SEQ, (long)SEQ * HID, (long)SEQ * HID);
}

// round 4
// speedup vs baseline: 7.2425x; 1.3026x over previous
#include <cuda_runtime.h>
#include <cstdint>

#define BATCH 4
#define SEQ   2048
#define CIN   1024
#define HID   1024

// ---------------- scratch (__device__ globals; alloc APIs forbidden) -------
__device__ float g_qp [BATCH * SEQ * HID];          // 32 MB (tf32-rounded)
__device__ float g_kp [BATCH * SEQ * HID];          // 32 MB (tf32-rounded)
__device__ float g_vp [BATCH * SEQ * HID];          // 32 MB (tf32-rounded)
__device__ float g_vpT[BATCH * SEQ * HID];          // 32 MB (per-batch [H][T])
__device__ float g_S  [(long)BATCH * SEQ * SEQ];    // 64 MB
__device__ float g_WqT[CIN * HID];                  // 4 MB  ([H][C], rounded)
__device__ float g_WkT[CIN * HID];                  // 4 MB

// ---------------- helpers ---------------------------------------------------
__device__ __forceinline__ uint32_t smem_u32(const void* p) {
    uint32_t r;
    asm("{ .reg .u64 t; cvta.to.shared.u64 t, %1; cvt.u32.u64 %0, t; }"
        : "=r"(r) : "l"(p));
    return r;
}
__device__ __forceinline__ void cpa16(uint32_t dst, const void* src) {
    asm volatile("cp.async.cg.shared.global [%0], [%1], 16;" :: "r"(dst), "l"(src));
}
__device__ __forceinline__ uint32_t f2tf(float x) {
    uint32_t r;
    asm("cvt.rna.tf32.f32 %0, %1;" : "=r"(r) : "f"(x));
    return r;
}
__device__ __forceinline__ float roundtf(float x) { return __uint_as_float(f2tf(x)); }
__device__ __forceinline__ void mma_tf32(float* c, const uint32_t* a, const uint32_t* b) {
    asm volatile("mma.sync.aligned.m16n8k8.row.col.f32.tf32.tf32.f32 "
                 "{%0,%1,%2,%3}, {%4,%5,%6,%7}, {%8,%9}, {%0,%1,%2,%3};"
                 : "+f"(c[0]), "+f"(c[1]), "+f"(c[2]), "+f"(c[3])
                 : "r"(a[0]), "r"(a[1]), "r"(a[2]), "r"(a[3]),
                   "r"(b[0]), "r"(b[1]));
}

// ---------------- tensor-core tf32 GEMM core --------------------------------
// C[M,N] = A[M,K] @ B[N,K]^T, K-contiguous. 128x128 CTA tile, BK=32,
// 3-stage cp.async pipeline, 8 warps (4x2), warp tile 32x64.
// CVTA: round A fragments from smem (A source is raw fp32).
// ROUND_OUT: round C to tf32 bits on store (output feeds a later GEMM).
#define NSTAGE      3
#define STAGE_FLTS  8192          // A 4096 + B 4096 floats (32 KB)
#define GEMM_SMEM   (NSTAGE * STAGE_FLTS * 4)   // 98304 B

template<bool CVTA, bool ROUND_OUT>
__device__ __forceinline__
void gemm_body(const float* __restrict__ A, const float* __restrict__ B,
               float* __restrict__ C, int ldA, int ldB, int ldC,
               int KT, int bm, int bn)
{
    extern __shared__ float sm[];
    const uint32_t sbase = smem_u32(sm);
    const int tid  = threadIdx.x;
    const int lane = tid & 31;
    const int wid  = tid >> 5;
    const int wm = (wid >> 1) * 32;
    const int wn = (wid & 1) * 64;
    const int qr = lane >> 2;
    const int qc = lane & 3;
    const int xm = qr << 2;

    const float* asrc[4]; const float* bsrc[4];
    uint32_t adst[4], bdst[4];
#pragma unroll
    for (int t = 0; t < 4; t++) {
        int e = tid + t * 256;
        int row = e >> 3;
        int kq  = (e & 7) * 4;
        uint32_t didx = (uint32_t)(row * 32 + (kq ^ ((row & 7) << 2)));
        asrc[t] = A + (long)(bm * 128 + row) * ldA + kq;
        bsrc[t] = B + (long)(bn * 128 + row) * ldB + kq;
        adst[t] = sbase + didx * 4;
        bdst[t] = sbase + (didx + 4096) * 4;
    }

    float acc[2][8][4];
#pragma unroll
    for (int mt = 0; mt < 2; mt++)
#pragma unroll
        for (int nt = 0; nt < 8; nt++)
#pragma unroll
            for (int i = 0; i < 4; i++) acc[mt][nt][i] = 0.0f;

#pragma unroll
    for (int s = 0; s < 2; s++) {
        uint32_t soff = (uint32_t)(s * STAGE_FLTS * 4);
#pragma unroll
        for (int t = 0; t < 4; t++) {
            cpa16(adst[t] + soff, asrc[t] + s * 32);
            cpa16(bdst[t] + soff, bsrc[t] + s * 32);
        }
        asm volatile("cp.async.commit_group;" ::: "memory");
    }

    for (int kt = 0; kt < KT; kt++) {
        asm volatile("cp.async.wait_group 1;" ::: "memory");
        __syncthreads();

        const float* As = sm + (kt % NSTAGE) * STAGE_FLTS;
        const float* Bs = As + 4096;

#pragma unroll
        for (int ks = 0; ks < 4; ks++) {
            const int k0 = ks * 8;
            const int c0 = (k0 + qc) ^ xm;
            const int c1 = (k0 + 4 + qc) ^ xm;

            uint32_t af[2][4];
#pragma unroll
            for (int mt = 0; mt < 2; mt++) {
                int r  = wm + mt * 16 + qr;
                int r8 = r + 8;
                if (CVTA) {
                    af[mt][0] = f2tf(As[r  * 32 + c0]);
                    af[mt][1] = f2tf(As[r8 * 32 + c0]);
                    af[mt][2] = f2tf(As[r  * 32 + c1]);
                    af[mt][3] = f2tf(As[r8 * 32 + c1]);
                } else {
                    af[mt][0] = __float_as_uint(As[r  * 32 + c0]);
                    af[mt][1] = __float_as_uint(As[r8 * 32 + c0]);
                    af[mt][2] = __float_as_uint(As[r  * 32 + c1]);
                    af[mt][3] = __float_as_uint(As[r8 * 32 + c1]);
                }
            }
            uint32_t bf[8][2];
#pragma unroll
            for (int nt = 0; nt < 8; nt++) {
                int n = wn + nt * 8 + qr;
                bf[nt][0] = __float_as_uint(Bs[n * 32 + c0]);
                bf[nt][1] = __float_as_uint(Bs[n * 32 + c1]);
            }
#pragma unroll
            for (int mt = 0; mt < 2; mt++)
#pragma unroll
                for (int nt = 0; nt < 8; nt++)
                    mma_tf32(acc[mt][nt], af[mt], bf[nt]);
        }

        int sf = kt + 2;
        if (sf < KT) {
            uint32_t soff = (uint32_t)((sf % NSTAGE) * STAGE_FLTS * 4);
#pragma unroll
            for (int t = 0; t < 4; t++) {
                cpa16(adst[t] + soff, asrc[t] + sf * 32);
                cpa16(bdst[t] + soff, bsrc[t] + sf * 32);
            }
        }
        asm volatile("cp.async.commit_group;" ::: "memory");
    }

#pragma unroll
    for (int mt = 0; mt < 2; mt++) {
        int r = bm * 128 + wm + mt * 16 + qr;
#pragma unroll
        for (int nt = 0; nt < 8; nt++) {
            int col = bn * 128 + wn + nt * 8 + 2 * qc;
            float o0 = acc[mt][nt][0], o1 = acc[mt][nt][1];
            float o2 = acc[mt][nt][2], o3 = acc[mt][nt][3];
            if (ROUND_OUT) { o0 = roundtf(o0); o1 = roundtf(o1);
                             o2 = roundtf(o2); o3 = roundtf(o3); }
            *(float2*)&C[(long)r * ldC + col]       = make_float2(o0, o1);
            *(float2*)&C[(long)(r + 8) * ldC + col] = make_float2(o2, o3);
        }
    }
}

// Fused projections: blockIdx.z selects (q,WqT)->qp, (k,WkT)->kp, (v,WqT)->vp.
__global__ __launch_bounds__(256, 2)
void proj_gemm(const float* __restrict__ qin, const float* __restrict__ kin,
               const float* __restrict__ vin, const float* __restrict__ WqT,
               const float* __restrict__ WkT, float* __restrict__ qp,
               float* __restrict__ kp, float* __restrict__ vp)
{
    const float* A; const float* B; float* C;
    if (blockIdx.z == 0)      { A = qin; B = WqT; C = qp; }
    else if (blockIdx.z == 1) { A = kin; B = WkT; C = kp; }
    else                      { A = vin; B = WqT; C = vp; }
    gemm_body<true, true>(A, B, C, CIN, CIN, HID, CIN / 32,
                          blockIdx.y, blockIdx.x);
}

// S = qp @ kp^T, triangular grid (blockIdx.x in [0,136)), blockIdx.z = batch.
__global__ __launch_bounds__(256, 2)
void s_gemm(const float* __restrict__ qp, const float* __restrict__ kp,
            float* __restrict__ S)
{
    int idx = blockIdx.x, acc = 0, bm = 0;
    while (acc + bm + 1 <= idx) { acc += bm + 1; bm++; }
    int bn = idx - acc;
    const long ob = (long)blockIdx.z * SEQ * HID;
    gemm_body<false, false>(qp + ob, kp + ob,
                            S + (long)blockIdx.z * SEQ * SEQ,
                            HID, HID, SEQ, HID / 32, bm, bn);
}

// out = P @ vpT^T, K causally limited to (bm+1)*128.
__global__ __launch_bounds__(256, 2)
void pv_gemm(const float* __restrict__ S, const float* __restrict__ vpT,
             float* __restrict__ out)
{
    const int bm = blockIdx.y, bn = blockIdx.x;
    const int KT = ((bm + 1) * 128) >> 5;
    gemm_body<false, false>(S + (long)blockIdx.z * SEQ * SEQ,
                            vpT + (long)blockIdx.z * SEQ * HID,
                            out + (long)blockIdx.z * SEQ * HID,
                            SEQ, SEQ, HID, KT, bm, bn);
}

// ---------------- transpose (rounds to tf32 on store) ----------------------
__global__ __launch_bounds__(256)
void transpose_k(const float* __restrict__ in, float* __restrict__ out,
                 int R, int C, long sIn, long sOut)
{
    __shared__ float tile[32][33];
    const int bz = blockIdx.z;
    in += (long)bz * sIn; out += (long)bz * sOut;
    const int c0 = blockIdx.x * 32, r0 = blockIdx.y * 32;
    const int tx = threadIdx.x & 31, ty = threadIdx.x >> 5;
#pragma unroll
    for (int i = 0; i < 32; i += 8)
        tile[ty + i][tx] = in[(long)(r0 + ty + i) * C + c0 + tx];
    __syncthreads();
#pragma unroll
    for (int i = 0; i < 32; i += 8)
        out[(long)(c0 + ty + i) * R + r0 + tx] = roundtf(tile[tx][ty + i]);
}

// ---------------- single-pass causal softmax --------------------------------
// One block per row; row cached in 8 regs/thread. Writes tf32-rounded P for
// valid cols, zeros only up to the end of the diagonal 128-block (PV never
// reads beyond its causal K-limit).
__global__ __launch_bounds__(256)
void softmax_fast(float* __restrict__ S, float scale)
{
    const int t = blockIdx.x, b = blockIdx.y;
    float* row = S + ((long)b * SEQ + t) * SEQ;
    const int n = t + 1;
    const int limit = ((t >> 7) + 1) << 7;
    const int tid = threadIdx.x;
    const int lane = tid & 31, wid = tid >> 5;

    __shared__ float redm[8], reds[8];

    float r[8];
#pragma unroll
    for (int j = 0; j < 8; j++) {
        int i = tid + j * 256;
        r[j] = (i < n) ? row[i] * scale : -1e30f;
    }

    float m = -1e30f;
#pragma unroll
    for (int j = 0; j < 8; j++) m = fmaxf(m, r[j]);
#pragma unroll
    for (int o = 16; o > 0; o >>= 1) m = fmaxf(m, __shfl_xor_sync(~0u, m, o));
    if (lane == 0) redm[wid] = m;
    __syncthreads();
#pragma unroll
    for (int j = 0; j < 8; j++) m = fmaxf(m, redm[j]);

    float sum = 0.0f;
#pragma unroll
    for (int j = 0; j < 8; j++) { r[j] = __expf(r[j] - m); sum += r[j]; }
#pragma unroll
    for (int o = 16; o > 0; o >>= 1) sum += __shfl_xor_sync(~0u, sum, o);
    if (lane == 0) reds[wid] = sum;
    __syncthreads();
    sum = 0.0f;
#pragma unroll
    for (int j = 0; j < 8; j++) sum += reds[j];
    const float inv = 1.0f / sum;

#pragma unroll
    for (int j = 0; j < 8; j++) {
        int i = tid + j * 256;
        if (i < limit) row[i] = (i < n) ? roundtf(r[j] * inv) : 0.0f;
    }
}

// ---------------- launch ---------------------------------------------------
extern "C" void kernel_launch(void* const* d_in, const int* in_sizes, int n_in,
                              void* d_out, int out_size)
{
    const float* kin = (const float*)d_in[1];
    const float* qin = (const float*)d_in[2];
    const float* vin = (const float*)d_in[3];
    const float* Wk  = (const float*)d_in[4];
    const float* Wq  = (const float*)d_in[5];
    float* out = (float*)d_out;

    float *qp, *kp, *vp, *vpT, *S, *WqT, *WkT;
    cudaGetSymbolAddress((void**)&qp,  g_qp);
    cudaGetSymbolAddress((void**)&kp,  g_kp);
    cudaGetSymbolAddress((void**)&vp,  g_vp);
    cudaGetSymbolAddress((void**)&vpT, g_vpT);
    cudaGetSymbolAddress((void**)&S,   g_S);
    cudaGetSymbolAddress((void**)&WqT, g_WqT);
    cudaGetSymbolAddress((void**)&WkT, g_WkT);

    cudaFuncSetAttribute(proj_gemm, cudaFuncAttributeMaxDynamicSharedMemorySize, GEMM_SMEM);
    cudaFuncSetAttribute(s_gemm,    cudaFuncAttributeMaxDynamicSharedMemorySize, GEMM_SMEM);
    cudaFuncSetAttribute(pv_gemm,   cudaFuncAttributeMaxDynamicSharedMemorySize, GEMM_SMEM);

    const int M = BATCH * SEQ;                 // 8192
    const float scale = 1.0f / 32.0f;          // HID^-0.5
    dim3 blk(256);

    dim3 gWT(HID / 32, CIN / 32, 1);
    transpose_k<<<gWT, blk>>>(Wq, WqT, CIN, HID, 0, 0);
    transpose_k<<<gWT, blk>>>(Wk, WkT, CIN, HID, 0, 0);

    dim3 gProj(HID / 128, M / 128, 3);
    proj_gemm<<<gProj, blk, GEMM_SMEM>>>(qin, kin, vin, WqT, WkT, qp, kp, vp);

    dim3 gVT(HID / 32, SEQ / 32, BATCH);
    transpose_k<<<gVT, blk>>>(vp, vpT, SEQ, HID, (long)SEQ * HID, (long)SEQ * HID);

    dim3 gS(136, 1, BATCH);
    s_gemm<<<gS, blk, GEMM_SMEM>>>(qp, kp, S);

    dim3 gSm(SEQ, BATCH);
    softmax_fast<<<gSm, blk>>>(S, scale);

    dim3 gPV(HID / 128, SEQ / 128, BATCH);
    pv_gemm<<<gPV, blk, GEMM_SMEM>>>(S, vpT, out);
}

// round 5
// speedup vs baseline: 7.7254x; 1.0667x over previous
#include <cuda_runtime.h>
#include <cstdint>

#define BATCH 4
#define SEQ   2048
#define CIN   1024
#define HID   1024

// ---------------- scratch (__device__ globals; alloc APIs forbidden) -------
__device__ float g_qp [BATCH * SEQ * HID];          // 32 MB (tf32-rounded, pre-scaled)
__device__ float g_kp [BATCH * SEQ * HID];          // 32 MB (tf32-rounded)
__device__ float g_vp [BATCH * SEQ * HID];          // 32 MB (tf32-rounded)
__device__ float g_vpT[BATCH * SEQ * HID];          // 32 MB (per-batch [H][T])
__device__ float g_S  [(long)BATCH * SEQ * SEQ];    // 64 MB
__device__ float g_WqT[CIN * HID];                  // 4 MB  ([H][C], rounded)
__device__ float g_WkT[CIN * HID];                  // 4 MB

// ---------------- helpers ---------------------------------------------------
__device__ __forceinline__ uint32_t smem_u32(const void* p) {
    uint32_t r;
    asm("{ .reg .u64 t; cvta.to.shared.u64 t, %1; cvt.u32.u64 %0, t; }"
        : "=r"(r) : "l"(p));
    return r;
}
__device__ __forceinline__ void cpa16(uint32_t dst, const void* src) {
    asm volatile("cp.async.cg.shared.global [%0], [%1], 16;" :: "r"(dst), "l"(src));
}
__device__ __forceinline__ uint32_t f2tf(float x) {
    uint32_t r;
    asm("cvt.rna.tf32.f32 %0, %1;" : "=r"(r) : "f"(x));
    return r;
}
__device__ __forceinline__ float roundtf(float x) { return __uint_as_float(f2tf(x)); }
__device__ __forceinline__ void mma_tf32(float* c, const uint32_t* a, const uint32_t* b) {
    asm volatile("mma.sync.aligned.m16n8k8.row.col.f32.tf32.tf32.f32 "
                 "{%0,%1,%2,%3}, {%4,%5,%6,%7}, {%8,%9}, {%0,%1,%2,%3};"
                 : "+f"(c[0]), "+f"(c[1]), "+f"(c[2]), "+f"(c[3])
                 : "r"(a[0]), "r"(a[1]), "r"(a[2]), "r"(a[3]),
                   "r"(b[0]), "r"(b[1]));
}

// ---------------- tensor-core tf32 GEMM core --------------------------------
// C[M,N] = A[M,K] @ B[N,K]^T, K-contiguous. 128x128 CTA tile, BK=32,
// 3-stage cp.async pipeline, 4 warps (2x2), warp tile 64x64 (CUTLASS-style).
// CVTA: round A fragments (A source is raw fp32). ROUND_OUT: tf32-round C.
// alphaOut: epilogue scale (exact when power of two).
#define NSTAGE      3
#define STAGE_FLTS  8192          // A 4096 + B 4096 floats (32 KB)
#define GEMM_SMEM   (NSTAGE * STAGE_FLTS * 4)   // 98304 B
#define GTHREADS    128

template<bool CVTA, bool ROUND_OUT>
__device__ __forceinline__
void gemm_body(const float* __restrict__ A, const float* __restrict__ B,
               float* __restrict__ C, int ldA, int ldB, int ldC,
               int KT, int bm, int bn, float alphaOut)
{
    extern __shared__ float sm[];
    const uint32_t sbase = smem_u32(sm);
    const int tid  = threadIdx.x;
    const int lane = tid & 31;
    const int wid  = tid >> 5;        // 0..3
    const int wm = (wid >> 1) * 64;   // warp row offset
    const int wn = (wid & 1) * 64;    // warp col offset
    const int qr = lane >> 2;         // 0..7
    const int qc = lane & 3;          // 0..3
    const int xm = qr << 2;

    // loaders: 8 float4 per thread per stage (128 threads x 8 = 1024 vec4)
    const float* asrc[8]; const float* bsrc[8];
    uint32_t adst[8], bdst[8];
#pragma unroll
    for (int t = 0; t < 8; t++) {
        int e = tid + t * GTHREADS;       // 0..1023
        int row = e >> 3;                 // 0..127
        int kq  = (e & 7) * 4;
        uint32_t didx = (uint32_t)(row * 32 + (kq ^ ((row & 7) << 2)));
        asrc[t] = A + (long)(bm * 128 + row) * ldA + kq;
        bsrc[t] = B + (long)(bn * 128 + row) * ldB + kq;
        adst[t] = sbase + didx * 4;
        bdst[t] = sbase + (didx + 4096) * 4;
    }

    float acc[4][8][4];
#pragma unroll
    for (int mt = 0; mt < 4; mt++)
#pragma unroll
        for (int nt = 0; nt < 8; nt++)
#pragma unroll
            for (int i = 0; i < 4; i++) acc[mt][nt][i] = 0.0f;

#pragma unroll
    for (int s = 0; s < 2; s++) {
        uint32_t soff = (uint32_t)(s * STAGE_FLTS * 4);
#pragma unroll
        for (int t = 0; t < 8; t++) {
            cpa16(adst[t] + soff, asrc[t] + s * 32);
            cpa16(bdst[t] + soff, bsrc[t] + s * 32);
        }
        asm volatile("cp.async.commit_group;" ::: "memory");
    }

    for (int kt = 0; kt < KT; kt++) {
        asm volatile("cp.async.wait_group 1;" ::: "memory");
        __syncthreads();

        const float* As = sm + (kt % NSTAGE) * STAGE_FLTS;
        const float* Bs = As + 4096;

#pragma unroll
        for (int ks = 0; ks < 4; ks++) {
            const int k0 = ks * 8;
            const int c0 = (k0 + qc) ^ xm;
            const int c1 = (k0 + 4 + qc) ^ xm;

            uint32_t af[4][4];
#pragma unroll
            for (int mt = 0; mt < 4; mt++) {
                int r  = wm + mt * 16 + qr;
                int r8 = r + 8;
                if (CVTA) {
                    af[mt][0] = f2tf(As[r  * 32 + c0]);
                    af[mt][1] = f2tf(As[r8 * 32 + c0]);
                    af[mt][2] = f2tf(As[r  * 32 + c1]);
                    af[mt][3] = f2tf(As[r8 * 32 + c1]);
                } else {
                    af[mt][0] = __float_as_uint(As[r  * 32 + c0]);
                    af[mt][1] = __float_as_uint(As[r8 * 32 + c0]);
                    af[mt][2] = __float_as_uint(As[r  * 32 + c1]);
                    af[mt][3] = __float_as_uint(As[r8 * 32 + c1]);
                }
            }
            uint32_t bf[8][2];
#pragma unroll
            for (int nt = 0; nt < 8; nt++) {
                int n = wn + nt * 8 + qr;
                bf[nt][0] = __float_as_uint(Bs[n * 32 + c0]);
                bf[nt][1] = __float_as_uint(Bs[n * 32 + c1]);
            }
#pragma unroll
            for (int mt = 0; mt < 4; mt++)
#pragma unroll
                for (int nt = 0; nt < 8; nt++)
                    mma_tf32(acc[mt][nt], af[mt], bf[nt]);
        }

        int sf = kt + 2;
        if (sf < KT) {
            uint32_t soff = (uint32_t)((sf % NSTAGE) * STAGE_FLTS * 4);
#pragma unroll
            for (int t = 0; t < 8; t++) {
                cpa16(adst[t] + soff, asrc[t] + sf * 32);
                cpa16(bdst[t] + soff, bsrc[t] + sf * 32);
            }
        }
        asm volatile("cp.async.commit_group;" ::: "memory");
    }

#pragma unroll
    for (int mt = 0; mt < 4; mt++) {
        int r = bm * 128 + wm + mt * 16 + qr;
#pragma unroll
        for (int nt = 0; nt < 8; nt++) {
            int col = bn * 128 + wn + nt * 8 + 2 * qc;
            float o0 = acc[mt][nt][0] * alphaOut, o1 = acc[mt][nt][1] * alphaOut;
            float o2 = acc[mt][nt][2] * alphaOut, o3 = acc[mt][nt][3] * alphaOut;
            if (ROUND_OUT) { o0 = roundtf(o0); o1 = roundtf(o1);
                             o2 = roundtf(o2); o3 = roundtf(o3); }
            *(float2*)&C[(long)r * ldC + col]       = make_float2(o0, o1);
            *(float2*)&C[(long)(r + 8) * ldC + col] = make_float2(o2, o3);
        }
    }
}

// Fused projections: z=0 (q,WqT)->qp (pre-scaled by 2^-5), z=1 (k,WkT)->kp,
// z=2 (v,WqT)->vp.
__global__ __launch_bounds__(GTHREADS, 2)
void proj_gemm(const float* __restrict__ qin, const float* __restrict__ kin,
               const float* __restrict__ vin, const float* __restrict__ WqT,
               const float* __restrict__ WkT, float* __restrict__ qp,
               float* __restrict__ kp, float* __restrict__ vp)
{
    const float* A; const float* B; float* C; float alpha = 1.0f;
    if (blockIdx.z == 0)      { A = qin; B = WqT; C = qp; alpha = 1.0f / 32.0f; }
    else if (blockIdx.z == 1) { A = kin; B = WkT; C = kp; }
    else                      { A = vin; B = WqT; C = vp; }
    gemm_body<true, true>(A, B, C, CIN, CIN, HID, CIN / 32,
                          blockIdx.y, blockIdx.x, alpha);
}

// S = qp @ kp^T (scale already folded into qp), triangular grid.
__global__ __launch_bounds__(GTHREADS, 2)
void s_gemm(const float* __restrict__ qp, const float* __restrict__ kp,
            float* __restrict__ S)
{
    int idx = blockIdx.x, acc = 0, bm = 0;
    while (acc + bm + 1 <= idx) { acc += bm + 1; bm++; }
    int bn = idx - acc;
    const long ob = (long)blockIdx.z * SEQ * HID;
    gemm_body<false, false>(qp + ob, kp + ob,
                            S + (long)blockIdx.z * SEQ * SEQ,
                            HID, HID, SEQ, HID / 32, bm, bn, 1.0f);
}

// out = P @ vpT^T, K causally limited to (bm+1)*128.
__global__ __launch_bounds__(GTHREADS, 2)
void pv_gemm(const float* __restrict__ S, const float* __restrict__ vpT,
             float* __restrict__ out)
{
    const int bm = blockIdx.y, bn = blockIdx.x;
    const int KT = ((bm + 1) * 128) >> 5;
    gemm_body<false, false>(S + (long)blockIdx.z * SEQ * SEQ,
                            vpT + (long)blockIdx.z * SEQ * HID,
                            out + (long)blockIdx.z * SEQ * HID,
                            SEQ, SEQ, HID, KT, bm, bn, 1.0f);
}

// ---------------- transpose (rounds to tf32 on store) ----------------------
__global__ __launch_bounds__(256)
void transpose_k(const float* __restrict__ in, float* __restrict__ out,
                 int R, int C, long sIn, long sOut)
{
    __shared__ float tile[32][33];
    const int bz = blockIdx.z;
    in += (long)bz * sIn; out += (long)bz * sOut;
    const int c0 = blockIdx.x * 32, r0 = blockIdx.y * 32;
    const int tx = threadIdx.x & 31, ty = threadIdx.x >> 5;
#pragma unroll
    for (int i = 0; i < 32; i += 8)
        tile[ty + i][tx] = in[(long)(r0 + ty + i) * C + c0 + tx];
    __syncthreads();
#pragma unroll
    for (int i = 0; i < 32; i += 8)
        out[(long)(c0 + ty + i) * R + r0 + tx] = roundtf(tile[tx][ty + i]);
}

// ---------------- single-pass causal softmax (input pre-scaled) ------------
__global__ __launch_bounds__(256)
void softmax_fast(float* __restrict__ S)
{
    const int t = blockIdx.x, b = blockIdx.y;
    float* row = S + ((long)b * SEQ + t) * SEQ;
    const int n = t + 1;
    const int limit = ((t >> 7) + 1) << 7;
    const int tid = threadIdx.x;
    const int lane = tid & 31, wid = tid >> 5;

    __shared__ float redm[8], reds[8];

    float r[8];
#pragma unroll
    for (int j = 0; j < 8; j++) {
        int i = tid + j * 256;
        r[j] = (i < n) ? row[i] : -1e30f;
    }

    float m = -1e30f;
#pragma unroll
    for (int j = 0; j < 8; j++) m = fmaxf(m, r[j]);
#pragma unroll
    for (int o = 16; o > 0; o >>= 1) m = fmaxf(m, __shfl_xor_sync(~0u, m, o));
    if (lane == 0) redm[wid] = m;
    __syncthreads();
#pragma unroll
    for (int j = 0; j < 8; j++) m = fmaxf(m, redm[j]);

    float sum = 0.0f;
#pragma unroll
    for (int j = 0; j < 8; j++) { r[j] = __expf(r[j] - m); sum += r[j]; }
#pragma unroll
    for (int o = 16; o > 0; o >>= 1) sum += __shfl_xor_sync(~0u, sum, o);
    if (lane == 0) reds[wid] = sum;
    __syncthreads();
    sum = 0.0f;
#pragma unroll
    for (int j = 0; j < 8; j++) sum += reds[j];
    const float inv = 1.0f / sum;

#pragma unroll
    for (int j = 0; j < 8; j++) {
        int i = tid + j * 256;
        if (i < limit) row[i] = (i < n) ? roundtf(r[j] * inv) : 0.0f;
    }
}

// ---------------- launch ---------------------------------------------------
extern "C" void kernel_launch(void* const* d_in, const int* in_sizes, int n_in,
                              void* d_out, int out_size)
{
    const float* kin = (const float*)d_in[1];
    const float* qin = (const float*)d_in[2];
    const float* vin = (const float*)d_in[3];
    const float* Wk  = (const float*)d_in[4];
    const float* Wq  = (const float*)d_in[5];
    float* out = (float*)d_out;

    float *qp, *kp, *vp, *vpT, *S, *WqT, *WkT;
    cudaGetSymbolAddress((void**)&qp,  g_qp);
    cudaGetSymbolAddress((void**)&kp,  g_kp);
    cudaGetSymbolAddress((void**)&vp,  g_vp);
    cudaGetSymbolAddress((void**)&vpT, g_vpT);
    cudaGetSymbolAddress((void**)&S,   g_S);
    cudaGetSymbolAddress((void**)&WqT, g_WqT);
    cudaGetSymbolAddress((void**)&WkT, g_WkT);

    cudaFuncSetAttribute(proj_gemm, cudaFuncAttributeMaxDynamicSharedMemorySize, GEMM_SMEM);
    cudaFuncSetAttribute(s_gemm,    cudaFuncAttributeMaxDynamicSharedMemorySize, GEMM_SMEM);
    cudaFuncSetAttribute(pv_gemm,   cudaFuncAttributeMaxDynamicSharedMemorySize, GEMM_SMEM);

    const int M = BATCH * SEQ;                 // 8192
    dim3 blk(256);
    dim3 gblk(GTHREADS);

    dim3 gWT(HID / 32, CIN / 32, 1);
    transpose_k<<<gWT, blk>>>(Wq, WqT, CIN, HID, 0, 0);
    transpose_k<<<gWT, blk>>>(Wk, WkT, CIN, HID, 0, 0);

    dim3 gProj(HID / 128, M / 128, 3);
    proj_gemm<<<gProj, gblk, GEMM_SMEM>>>(qin, kin, vin, WqT, WkT, qp, kp, vp);

    dim3 gVT(HID / 32, SEQ / 32, BATCH);
    transpose_k<<<gVT, blk>>>(vp, vpT, SEQ, HID, (long)SEQ * HID, (long)SEQ * HID);

    dim3 gS(136, 1, BATCH);
    s_gemm<<<gS, gblk, GEMM_SMEM>>>(qp, kp, S);

    dim3 gSm(SEQ, BATCH);
    softmax_fast<<<gSm, blk>>>(S);

    dim3 gPV(HID / 128, SEQ / 128, BATCH);
    pv_gemm<<<gPV, gblk, GEMM_SMEM>>>(S, vpT, out);
}

// round 6
// speedup vs baseline: 8.0470x; 1.0416x over previous
#include <cuda_runtime.h>
#include <cstdint>

#define BATCH 4
#define SEQ   2048
#define CIN   1024
#define HID   1024

// ---------------- scratch (__device__ globals; alloc APIs forbidden) -------
__device__ float g_qp [BATCH * SEQ * HID];          // 32 MB (tf32-rounded, pre-scaled 2^-5)
__device__ float g_kp [BATCH * SEQ * HID];          // 32 MB (tf32-rounded)
__device__ float g_vp [BATCH * SEQ * HID];          // 32 MB (tf32-rounded)
__device__ float g_S  [(long)BATCH * SEQ * SEQ];    // 64 MB

// ---------------- helpers ---------------------------------------------------
__device__ __forceinline__ uint32_t smem_u32(const void* p) {
    uint32_t r;
    asm("{ .reg .u64 t; cvta.to.shared.u64 t, %1; cvt.u32.u64 %0, t; }"
        : "=r"(r) : "l"(p));
    return r;
}
__device__ __forceinline__ void cpa16(uint32_t dst, const void* src) {
    asm volatile("cp.async.cg.shared.global [%0], [%1], 16;" :: "r"(dst), "l"(src));
}
__device__ __forceinline__ uint32_t f2tf(float x) {
    uint32_t r;
    asm("cvt.rna.tf32.f32 %0, %1;" : "=r"(r) : "f"(x));
    return r;
}
__device__ __forceinline__ float roundtf(float x) { return __uint_as_float(f2tf(x)); }
__device__ __forceinline__ void mma_tf32(float* c, const uint32_t* a, const uint32_t* b) {
    asm volatile("mma.sync.aligned.m16n8k8.row.col.f32.tf32.tf32.f32 "
                 "{%0,%1,%2,%3}, {%4,%5,%6,%7}, {%8,%9}, {%0,%1,%2,%3};"
                 : "+f"(c[0]), "+f"(c[1]), "+f"(c[2]), "+f"(c[3])
                 : "r"(a[0]), "r"(a[1]), "r"(a[2]), "r"(a[3]),
                   "r"(b[0]), "r"(b[1]));
}

// ---------------- tensor-core tf32 GEMM core --------------------------------
// C[M,N] = A[M,K] @ Bop, 128x128 CTA tile, BK=32, 3-stage cp.async pipeline,
// 4 warps (2x2), warp tile 64x64.
//   BNN=false: Bop = B[N,K]^T with B row-major K-contiguous (NT).
//   BNN=true : Bop = B[K,N]   with B row-major N-contiguous (NN).
// CVTA: RNA-round A fragments (A source is raw fp32).
// ROUND_OUT: tf32-round C on store. alphaOut: epilogue scale.
#define NSTAGE      3
#define STAGE_FLTS  8192          // A 4096 + B 4096 floats (32 KB)
#define GEMM_SMEM   (NSTAGE * STAGE_FLTS * 4)   // 98304 B
#define GTHREADS    128

template<bool CVTA, bool ROUND_OUT, bool BNN>
__device__ __forceinline__
void gemm_body(const float* __restrict__ A, const float* __restrict__ B,
               float* __restrict__ C, int ldA, int ldB, int ldC,
               int KT, int bm, int bn, float alphaOut)
{
    extern __shared__ float sm[];
    const uint32_t sbase = smem_u32(sm);
    const int tid  = threadIdx.x;
    const int lane = tid & 31;
    const int wid  = tid >> 5;        // 0..3
    const int wm = (wid >> 1) * 64;
    const int wn = (wid & 1) * 64;
    const int qr = lane >> 2;         // 0..7
    const int qc = lane & 3;          // 0..3
    const int xm = qr << 2;

    // loaders: 8 float4 per thread per stage (128 threads x 8 = 1024 vec4)
    const float* asrc[8]; const float* bsrc[8];
    uint32_t adst[8], bdst[8];
    const long bStep = BNN ? (long)32 * ldB : 32;   // per-stage B advance
#pragma unroll
    for (int t = 0; t < 8; t++) {
        int e = tid + t * GTHREADS;       // 0..1023
        {   // A: rows 0..127, k quads
            int row = e >> 3;
            int kq  = (e & 7) * 4;
            uint32_t didx = (uint32_t)(row * 32 + (kq ^ ((row & 7) << 2)));
            asrc[t] = A + (long)(bm * 128 + row) * ldA + kq;
            adst[t] = sbase + didx * 4;
        }
        if (BNN) {  // B tile [k=0..31][n=0..127], swizzle n^=((k&3)<<3)
            int k  = e >> 5;              // 0..31
            int n4 = (e & 31) * 4;        // 0..124
            uint32_t didx = (uint32_t)(k * 128 + (n4 ^ ((k & 3) << 3)));
            bsrc[t] = B + (long)k * ldB + bn * 128 + n4;
            bdst[t] = sbase + (didx + 4096) * 4;
        } else {    // B tile [n=0..127][k=0..31], same swizzle as A
            int row = e >> 3;
            int kq  = (e & 7) * 4;
            uint32_t didx = (uint32_t)(row * 32 + (kq ^ ((row & 7) << 2)));
            bsrc[t] = B + (long)(bn * 128 + row) * ldB + kq;
            bdst[t] = sbase + (didx + 4096) * 4;
        }
    }

    float acc[4][8][4];
#pragma unroll
    for (int mt = 0; mt < 4; mt++)
#pragma unroll
        for (int nt = 0; nt < 8; nt++)
#pragma unroll
            for (int i = 0; i < 4; i++) acc[mt][nt][i] = 0.0f;

    // NN fragment column pre-swizzle (per thread, per nt)
    int npr[8];
    if (BNN) {
#pragma unroll
        for (int nt = 0; nt < 8; nt++)
            npr[nt] = (wn + nt * 8 + qr) ^ (qc << 3);
    }

#pragma unroll
    for (int s = 0; s < 2; s++) {
        uint32_t soff = (uint32_t)(s * STAGE_FLTS * 4);
#pragma unroll
        for (int t = 0; t < 8; t++) {
            cpa16(adst[t] + soff, asrc[t] + s * 32);
            cpa16(bdst[t] + soff, bsrc[t] + s * bStep);
        }
        asm volatile("cp.async.commit_group;" ::: "memory");
    }

    for (int kt = 0; kt < KT; kt++) {
        asm volatile("cp.async.wait_group 1;" ::: "memory");
        __syncthreads();

        const float* As = sm + (kt % NSTAGE) * STAGE_FLTS;
        const float* Bs = As + 4096;

#pragma unroll
        for (int ks = 0; ks < 4; ks++) {
            const int k0 = ks * 8;
            const int c0 = (k0 + qc) ^ xm;
            const int c1 = (k0 + 4 + qc) ^ xm;

            uint32_t af[4][4];
#pragma unroll
            for (int mt = 0; mt < 4; mt++) {
                int r  = wm + mt * 16 + qr;
                int r8 = r + 8;
                if (CVTA) {
                    af[mt][0] = f2tf(As[r  * 32 + c0]);
                    af[mt][1] = f2tf(As[r8 * 32 + c0]);
                    af[mt][2] = f2tf(As[r  * 32 + c1]);
                    af[mt][3] = f2tf(As[r8 * 32 + c1]);
                } else {
                    af[mt][0] = __float_as_uint(As[r  * 32 + c0]);
                    af[mt][1] = __float_as_uint(As[r8 * 32 + c0]);
                    af[mt][2] = __float_as_uint(As[r  * 32 + c1]);
                    af[mt][3] = __float_as_uint(As[r8 * 32 + c1]);
                }
            }
            uint32_t bf[8][2];
#pragma unroll
            for (int nt = 0; nt < 8; nt++) {
                if (BNN) {
                    bf[nt][0] = __float_as_uint(Bs[(k0 + qc)     * 128 + npr[nt]]);
                    bf[nt][1] = __float_as_uint(Bs[(k0 + 4 + qc) * 128 + npr[nt]]);
                } else {
                    int n = wn + nt * 8 + qr;
                    bf[nt][0] = __float_as_uint(Bs[n * 32 + c0]);
                    bf[nt][1] = __float_as_uint(Bs[n * 32 + c1]);
                }
            }
#pragma unroll
            for (int mt = 0; mt < 4; mt++)
#pragma unroll
                for (int nt = 0; nt < 8; nt++)
                    mma_tf32(acc[mt][nt], af[mt], bf[nt]);
        }

        int sf = kt + 2;
        if (sf < KT) {
            uint32_t soff = (uint32_t)((sf % NSTAGE) * STAGE_FLTS * 4);
#pragma unroll
            for (int t = 0; t < 8; t++) {
                cpa16(adst[t] + soff, asrc[t] + sf * 32);
                cpa16(bdst[t] + soff, bsrc[t] + sf * bStep);
            }
        }
        asm volatile("cp.async.commit_group;" ::: "memory");
    }

#pragma unroll
    for (int mt = 0; mt < 4; mt++) {
        int r = bm * 128 + wm + mt * 16 + qr;
#pragma unroll
        for (int nt = 0; nt < 8; nt++) {
            int col = bn * 128 + wn + nt * 8 + 2 * qc;
            float o0 = acc[mt][nt][0] * alphaOut, o1 = acc[mt][nt][1] * alphaOut;
            float o2 = acc[mt][nt][2] * alphaOut, o3 = acc[mt][nt][3] * alphaOut;
            if (ROUND_OUT) { o0 = roundtf(o0); o1 = roundtf(o1);
                             o2 = roundtf(o2); o3 = roundtf(o3); }
            *(float2*)&C[(long)r * ldC + col]       = make_float2(o0, o1);
            *(float2*)&C[(long)(r + 8) * ldC + col] = make_float2(o2, o3);
        }
    }
}

// Fused projections (NN: B = W[C][H] read directly, no transpose):
// z=0 (q,Wq)->qp (pre-scaled 2^-5), z=1 (k,Wk)->kp, z=2 (v,Wq)->vp.
__global__ __launch_bounds__(GTHREADS, 2)
void proj_gemm(const float* __restrict__ qin, const float* __restrict__ kin,
               const float* __restrict__ vin, const float* __restrict__ Wq,
               const float* __restrict__ Wk, float* __restrict__ qp,
               float* __restrict__ kp, float* __restrict__ vp)
{
    const float* A; const float* B; float* C; float alpha = 1.0f;
    if (blockIdx.z == 0)      { A = qin; B = Wq; C = qp; alpha = 1.0f / 32.0f; }
    else if (blockIdx.z == 1) { A = kin; B = Wk; C = kp; }
    else                      { A = vin; B = Wq; C = vp; }
    gemm_body<true, true, true>(A, B, C, CIN, HID, HID, CIN / 32,
                                blockIdx.y, blockIdx.x, alpha);
}

// S = qp @ kp^T (scale folded into qp), triangular grid, heavy blocks first.
__global__ __launch_bounds__(GTHREADS, 2)
void s_gemm(const float* __restrict__ qp, const float* __restrict__ kp,
            float* __restrict__ S)
{
    int idx = 135 - blockIdx.x;           // heavy (high-bm) first
    int acc = 0, bm = 0;
    while (acc + bm + 1 <= idx) { acc += bm + 1; bm++; }
    int bn = idx - acc;
    const long ob = (long)blockIdx.z * SEQ * HID;
    gemm_body<false, false, false>(qp + ob, kp + ob,
                                   S + (long)blockIdx.z * SEQ * SEQ,
                                   HID, HID, SEQ, HID / 32, bm, bn, 1.0f);
}

// out = P @ vp (NN: vp[s][h] read directly), K causally limited, heavy first.
__global__ __launch_bounds__(GTHREADS, 2)
void pv_gemm(const float* __restrict__ S, const float* __restrict__ vp,
             float* __restrict__ out)
{
    const int bm = (int)(gridDim.y - 1 - blockIdx.y);   // heavy (high-bm) first
    const int bn = blockIdx.x;
    const int KT = (bm + 1) * 4;          // ((bm+1)*128)/32
    gemm_body<false, false, true>(S + (long)blockIdx.z * SEQ * SEQ,
                                  vp + (long)blockIdx.z * SEQ * HID,
                                  out + (long)blockIdx.z * SEQ * HID,
                                  SEQ, HID, HID, KT, bm, bn, 1.0f);
}

// ---------------- single-pass causal softmax (input pre-scaled) ------------
// Writes tf32-rounded P for valid cols; zeros only to the end of the diagonal
// 128-block (PV never reads beyond its causal K-limit).
__global__ __launch_bounds__(256)
void softmax_fast(float* __restrict__ S)
{
    const int t = blockIdx.x, b = blockIdx.y;
    float* row = S + ((long)b * SEQ + t) * SEQ;
    const int n = t + 1;
    const int limit = ((t >> 7) + 1) << 7;
    const int tid = threadIdx.x;
    const int lane = tid & 31, wid = tid >> 5;

    __shared__ float redm[8], reds[8];

    float r[8];
#pragma unroll
    for (int j = 0; j < 8; j++) {
        int i = tid + j * 256;
        r[j] = (i < n) ? row[i] : -1e30f;
    }

    float m = -1e30f;
#pragma unroll
    for (int j = 0; j < 8; j++) m = fmaxf(m, r[j]);
#pragma unroll
    for (int o = 16; o > 0; o >>= 1) m = fmaxf(m, __shfl_xor_sync(~0u, m, o));
    if (lane == 0) redm[wid] = m;
    __syncthreads();
#pragma unroll
    for (int j = 0; j < 8; j++) m = fmaxf(m, redm[j]);

    float sum = 0.0f;
#pragma unroll
    for (int j = 0; j < 8; j++) { r[j] = __expf(r[j] - m); sum += r[j]; }
#pragma unroll
    for (int o = 16; o > 0; o >>= 1) sum += __shfl_xor_sync(~0u, sum, o);
    if (lane == 0) reds[wid] = sum;
    __syncthreads();
    sum = 0.0f;
#pragma unroll
    for (int j = 0; j < 8; j++) sum += reds[j];
    const float inv = 1.0f / sum;

#pragma unroll
    for (int j = 0; j < 8; j++) {
        int i = tid + j * 256;
        if (i < limit) row[i] = (i < n) ? roundtf(r[j] * inv) : 0.0f;
    }
}

// ---------------- launch ---------------------------------------------------
extern "C" void kernel_launch(void* const* d_in, const int* in_sizes, int n_in,
                              void* d_out, int out_size)
{
    const float* kin = (const float*)d_in[1];
    const float* qin = (const float*)d_in[2];
    const float* vin = (const float*)d_in[3];
    const float* Wk  = (const float*)d_in[4];
    const float* Wq  = (const float*)d_in[5];
    float* out = (float*)d_out;

    float *qp, *kp, *vp, *S;
    cudaGetSymbolAddress((void**)&qp, g_qp);
    cudaGetSymbolAddress((void**)&kp, g_kp);
    cudaGetSymbolAddress((void**)&vp, g_vp);
    cudaGetSymbolAddress((void**)&S,  g_S);

    cudaFuncSetAttribute(proj_gemm, cudaFuncAttributeMaxDynamicSharedMemorySize, GEMM_SMEM);
    cudaFuncSetAttribute(s_gemm,    cudaFuncAttributeMaxDynamicSharedMemorySize, GEMM_SMEM);
    cudaFuncSetAttribute(pv_gemm,   cudaFuncAttributeMaxDynamicSharedMemorySize, GEMM_SMEM);

    const int M = BATCH * SEQ;                 // 8192
    dim3 blk(256);
    dim3 gblk(GTHREADS);

    dim3 gProj(HID / 128, M / 128, 3);
    proj_gemm<<<gProj, gblk, GEMM_SMEM>>>(qin, kin, vin, Wq, Wk, qp, kp, vp);

    dim3 gS(136, 1, BATCH);
    s_gemm<<<gS, gblk, GEMM_SMEM>>>(qp, kp, S);

    dim3 gSm(SEQ, BATCH);
    softmax_fast<<<gSm, blk>>>(S);

    dim3 gPV(HID / 128, SEQ / 128, BATCH);
    pv_gemm<<<gPV, gblk, GEMM_SMEM>>>(S, vp, out);
}

// round 7
// speedup vs baseline: 8.1538x; 1.0133x over previous
#include <cuda_runtime.h>
#include <cstdint>

#define BATCH 4
#define SEQ   2048
#define CIN   1024
#define HID   1024

// ---------------- scratch (__device__ globals; alloc APIs forbidden) -------
__device__ float g_qp [BATCH * SEQ * HID];          // 32 MB (tf32-rounded, pre-scaled 2^-5)
__device__ float g_kp [BATCH * SEQ * HID];          // 32 MB (tf32-rounded)
__device__ float g_vp [BATCH * SEQ * HID];          // 32 MB (tf32-rounded)
__device__ float g_S  [(long)BATCH * SEQ * SEQ];    // 64 MB

// ---------------- helpers ---------------------------------------------------
__device__ __forceinline__ uint32_t smem_u32(const void* p) {
    uint32_t r;
    asm("{ .reg .u64 t; cvta.to.shared.u64 t, %1; cvt.u32.u64 %0, t; }"
        : "=r"(r) : "l"(p));
    return r;
}
__device__ __forceinline__ void cpa16(uint32_t dst, const void* src) {
    asm volatile("cp.async.cg.shared.global [%0], [%1], 16;" :: "r"(dst), "l"(src));
}
__device__ __forceinline__ uint32_t f2tf(float x) {
    uint32_t r;
    asm("cvt.rna.tf32.f32 %0, %1;" : "=r"(r) : "f"(x));
    return r;
}
__device__ __forceinline__ float roundtf(float x) { return __uint_as_float(f2tf(x)); }
__device__ __forceinline__ void mma_tf32(float* c, const uint32_t* a, const uint32_t* b) {
    asm volatile("mma.sync.aligned.m16n8k8.row.col.f32.tf32.tf32.f32 "
                 "{%0,%1,%2,%3}, {%4,%5,%6,%7}, {%8,%9}, {%0,%1,%2,%3};"
                 : "+f"(c[0]), "+f"(c[1]), "+f"(c[2]), "+f"(c[3])
                 : "r"(a[0]), "r"(a[1]), "r"(a[2]), "r"(a[3]),
                   "r"(b[0]), "r"(b[1]));
}

// ---------------- tensor-core tf32 GEMM core --------------------------------
// C[M,N] = A[M,K] @ Bop, 128x128 CTA tile, BK=32, 3-stage cp.async pipeline,
// 4 warps (2x2), warp tile 64x64, explicit fragment double-buffering.
//   BNN=false: Bop = B[N,K]^T (B row-major K-contiguous).
//   BNN=true : Bop = B[K,N]   (B row-major N-contiguous).
#define NSTAGE      3
#define STAGE_FLTS  8192          // A 4096 + B 4096 floats (32 KB)
#define GEMM_SMEM   (NSTAGE * STAGE_FLTS * 4)   // 98304 B
#define GTHREADS    128

template<bool CVTA, bool ROUND_OUT, bool BNN>
__device__ __forceinline__
void gemm_body(const float* __restrict__ A, const float* __restrict__ B,
               float* __restrict__ C, int ldA, int ldB, int ldC,
               int KT, int bm, int bn, float alphaOut)
{
    extern __shared__ float sm[];
    const uint32_t sbase = smem_u32(sm);
    const int tid  = threadIdx.x;
    const int lane = tid & 31;
    const int wid  = tid >> 5;        // 0..3
    const int wm = (wid >> 1) * 64;
    const int wn = (wid & 1) * 64;
    const int qr = lane >> 2;         // 0..7
    const int qc = lane & 3;          // 0..3
    const int xm = qr << 2;

    // ---- loader bases (strength-reduced: 1 base + 1 stride per operand) ----
    // A (and NT-B): thread covers rows arow+16t, t=0..7; row&7 invariant so
    // the swizzled smem offset advances by a constant 2048 B.
    const int arow = tid >> 3;            // 0..15
    const int akq  = (tid & 7) * 4;
    const float* Abase = A + (long)(bm * 128 + arow) * ldA + akq;
    const long aStride = (long)16 * ldA;
    const uint32_t adst0 = sbase + (uint32_t)(arow * 32 + (akq ^ ((arow & 7) << 2))) * 4;

    const float* Bbase; long bStride; long bStageStep; uint32_t bdst0;
    if (BNN) {   // tile [k][n], k = bk+4t (k&3 invariant), swizzle n^=((k&3)<<3)
        const int bk  = tid >> 5;         // 0..3
        const int bn4 = (tid & 31) * 4;
        Bbase = B + (long)bk * ldB + bn * 128 + bn4;
        bStride = (long)4 * ldB;
        bStageStep = (long)32 * ldB;
        bdst0 = sbase + 16384u + (uint32_t)(bk * 128 + (bn4 ^ ((bk & 3) << 3))) * 4;
    } else {     // tile [n][k], same geometry as A
        Bbase = B + (long)(bn * 128 + arow) * ldB + akq;
        bStride = (long)16 * ldB;
        bStageStep = 32;
        bdst0 = sbase + 16384u + (uint32_t)(arow * 32 + (akq ^ ((arow & 7) << 2))) * 4;
    }

    auto issue_stage = [&](int s) {
        const uint32_t soff = (uint32_t)((s % NSTAGE) * (STAGE_FLTS * 4));
        const float* ap = Abase + s * 32;
        uint32_t ad = adst0 + soff;
#pragma unroll
        for (int t = 0; t < 8; t++) { cpa16(ad, ap); ap += aStride; ad += 2048; }
        const float* bp = Bbase + s * bStageStep;
        uint32_t bd = bdst0 + soff;
#pragma unroll
        for (int t = 0; t < 8; t++) { cpa16(bd, bp); bp += bStride; bd += 2048; }
    };

    // NN fragment column pre-swizzle
    int npr[8];
    if (BNN) {
#pragma unroll
        for (int nt = 0; nt < 8; nt++)
            npr[nt] = (wn + nt * 8 + qr) ^ (qc << 3);
    }

    auto load_frags = [&](const float* As, const float* Bs, int ks,
                          uint32_t af[4][4], uint32_t bf[8][2]) {
        const int k0 = ks * 8;
        const int c0 = (k0 + qc) ^ xm;
        const int c1 = (k0 + 4 + qc) ^ xm;
#pragma unroll
        for (int mt = 0; mt < 4; mt++) {
            int r  = wm + mt * 16 + qr;
            int r8 = r + 8;
            if (CVTA) {
                af[mt][0] = f2tf(As[r  * 32 + c0]);
                af[mt][1] = f2tf(As[r8 * 32 + c0]);
                af[mt][2] = f2tf(As[r  * 32 + c1]);
                af[mt][3] = f2tf(As[r8 * 32 + c1]);
            } else {
                af[mt][0] = __float_as_uint(As[r  * 32 + c0]);
                af[mt][1] = __float_as_uint(As[r8 * 32 + c0]);
                af[mt][2] = __float_as_uint(As[r  * 32 + c1]);
                af[mt][3] = __float_as_uint(As[r8 * 32 + c1]);
            }
        }
#pragma unroll
        for (int nt = 0; nt < 8; nt++) {
            if (BNN) {
                bf[nt][0] = __float_as_uint(Bs[(k0 + qc)     * 128 + npr[nt]]);
                bf[nt][1] = __float_as_uint(Bs[(k0 + 4 + qc) * 128 + npr[nt]]);
            } else {
                int n = wn + nt * 8 + qr;
                bf[nt][0] = __float_as_uint(Bs[n * 32 + c0]);
                bf[nt][1] = __float_as_uint(Bs[n * 32 + c1]);
            }
        }
    };

    float acc[4][8][4];
#pragma unroll
    for (int mt = 0; mt < 4; mt++)
#pragma unroll
        for (int nt = 0; nt < 8; nt++)
#pragma unroll
            for (int i = 0; i < 4; i++) acc[mt][nt][i] = 0.0f;

    auto run_mma = [&](uint32_t af[4][4], uint32_t bf[8][2]) {
#pragma unroll
        for (int mt = 0; mt < 4; mt++)
#pragma unroll
            for (int nt = 0; nt < 8; nt++)
                mma_tf32(acc[mt][nt], af[mt], bf[nt]);
    };

    // prologue: stages 0 and 1
#pragma unroll
    for (int s = 0; s < 2; s++) {
        issue_stage(s);
        asm volatile("cp.async.commit_group;" ::: "memory");
    }

    for (int kt = 0; kt < KT; kt++) {
        asm volatile("cp.async.wait_group 1;" ::: "memory");
        __syncthreads();

        const float* As = sm + (kt % NSTAGE) * STAGE_FLTS;
        const float* Bs = As + 4096;

        uint32_t afA[4][4], bfA[8][2], afB[4][4], bfB[8][2];
        load_frags(As, Bs, 0, afA, bfA);

        // prefetch stage kt+2 now: gmem loads overlap the whole MMA body
        int sf = kt + 2;
        if (sf < KT) issue_stage(sf);
        asm volatile("cp.async.commit_group;" ::: "memory");

        load_frags(As, Bs, 1, afB, bfB);
        run_mma(afA, bfA);
        load_frags(As, Bs, 2, afA, bfA);
        run_mma(afB, bfB);
        load_frags(As, Bs, 3, afB, bfB);
        run_mma(afA, bfA);
        run_mma(afB, bfB);
    }

#pragma unroll
    for (int mt = 0; mt < 4; mt++) {
        int r = bm * 128 + wm + mt * 16 + qr;
#pragma unroll
        for (int nt = 0; nt < 8; nt++) {
            int col = bn * 128 + wn + nt * 8 + 2 * qc;
            float o0 = acc[mt][nt][0] * alphaOut, o1 = acc[mt][nt][1] * alphaOut;
            float o2 = acc[mt][nt][2] * alphaOut, o3 = acc[mt][nt][3] * alphaOut;
            if (ROUND_OUT) { o0 = roundtf(o0); o1 = roundtf(o1);
                             o2 = roundtf(o2); o3 = roundtf(o3); }
            *(float2*)&C[(long)r * ldC + col]       = make_float2(o0, o1);
            *(float2*)&C[(long)(r + 8) * ldC + col] = make_float2(o2, o3);
        }
    }
}

// Fused projections (NN: W[C][H] read directly):
// z=0 (q,Wq)->qp (pre-scaled 2^-5), z=1 (k,Wk)->kp, z=2 (v,Wq)->vp.
__global__ __launch_bounds__(GTHREADS, 2)
void proj_gemm(const float* __restrict__ qin, const float* __restrict__ kin,
               const float* __restrict__ vin, const float* __restrict__ Wq,
               const float* __restrict__ Wk, float* __restrict__ qp,
               float* __restrict__ kp, float* __restrict__ vp)
{
    const float* A; const float* B; float* C; float alpha = 1.0f;
    if (blockIdx.z == 0)      { A = qin; B = Wq; C = qp; alpha = 1.0f / 32.0f; }
    else if (blockIdx.z == 1) { A = kin; B = Wk; C = kp; }
    else                      { A = vin; B = Wq; C = vp; }
    gemm_body<true, true, true>(A, B, C, CIN, HID, HID, CIN / 32,
                                blockIdx.y, blockIdx.x, alpha);
}

// S = qp @ kp^T (scale folded into qp), triangular grid, heavy blocks first.
__global__ __launch_bounds__(GTHREADS, 2)
void s_gemm(const float* __restrict__ qp, const float* __restrict__ kp,
            float* __restrict__ S)
{
    int idx = 135 - blockIdx.x;           // heavy (high-bm) first
    int acc = 0, bm = 0;
    while (acc + bm + 1 <= idx) { acc += bm + 1; bm++; }
    int bn = idx - acc;
    const long ob = (long)blockIdx.z * SEQ * HID;
    gemm_body<false, false, false>(qp + ob, kp + ob,
                                   S + (long)blockIdx.z * SEQ * SEQ,
                                   HID, HID, SEQ, HID / 32, bm, bn, 1.0f);
}

// out = P @ vp (NN), K causally limited, heavy blocks first.
__global__ __launch_bounds__(GTHREADS, 2)
void pv_gemm(const float* __restrict__ S, const float* __restrict__ vp,
             float* __restrict__ out)
{
    const int bm = (int)(gridDim.y - 1 - blockIdx.y);   // heavy first
    const int bn = blockIdx.x;
    const int KT = (bm + 1) * 4;
    gemm_body<false, false, true>(S + (long)blockIdx.z * SEQ * SEQ,
                                  vp + (long)blockIdx.z * SEQ * HID,
                                  out + (long)blockIdx.z * SEQ * HID,
                                  SEQ, HID, HID, KT, bm, bn, 1.0f);
}

// ---------------- single-pass causal softmax (input pre-scaled) ------------
__global__ __launch_bounds__(256)
void softmax_fast(float* __restrict__ S)
{
    const int t = blockIdx.x, b = blockIdx.y;
    float* row = S + ((long)b * SEQ + t) * SEQ;
    const int n = t + 1;
    const int limit = ((t >> 7) + 1) << 7;
    const int tid = threadIdx.x;
    const int lane = tid & 31, wid = tid >> 5;

    __shared__ float redm[8], reds[8];

    float r[8];
#pragma unroll
    for (int j = 0; j < 8; j++) {
        int i = tid + j * 256;
        r[j] = (i < n) ? row[i] : -1e30f;
    }

    float m = -1e30f;
#pragma unroll
    for (int j = 0; j < 8; j++) m = fmaxf(m, r[j]);
#pragma unroll
    for (int o = 16; o > 0; o >>= 1) m = fmaxf(m, __shfl_xor_sync(~0u, m, o));
    if (lane == 0) redm[wid] = m;
    __syncthreads();
#pragma unroll
    for (int j = 0; j < 8; j++) m = fmaxf(m, redm[j]);

    float sum = 0.0f;
#pragma unroll
    for (int j = 0; j < 8; j++) { r[j] = __expf(r[j] - m); sum += r[j]; }
#pragma unroll
    for (int o = 16; o > 0; o >>= 1) sum += __shfl_xor_sync(~0u, sum, o);
    if (lane == 0) reds[wid] = sum;
    __syncthreads();
    sum = 0.0f;
#pragma unroll
    for (int j = 0; j < 8; j++) sum += reds[j];
    const float inv = 1.0f / sum;

#pragma unroll
    for (int j = 0; j < 8; j++) {
        int i = tid + j * 256;
        if (i < limit) row[i] = (i < n) ? roundtf(r[j] * inv) : 0.0f;
    }
}

// ---------------- launch ---------------------------------------------------
extern "C" void kernel_launch(void* const* d_in, const int* in_sizes, int n_in,
                              void* d_out, int out_size)
{
    const float* kin = (const float*)d_in[1];
    const float* qin = (const float*)d_in[2];
    const float* vin = (const float*)d_in[3];
    const float* Wk  = (const float*)d_in[4];
    const float* Wq  = (const float*)d_in[5];
    float* out = (float*)d_out;

    float *qp, *kp, *vp, *S;
    cudaGetSymbolAddress((void**)&qp, g_qp);
    cudaGetSymbolAddress((void**)&kp, g_kp);
    cudaGetSymbolAddress((void**)&vp, g_vp);
    cudaGetSymbolAddress((void**)&S,  g_S);

    cudaFuncSetAttribute(proj_gemm, cudaFuncAttributeMaxDynamicSharedMemorySize, GEMM_SMEM);
    cudaFuncSetAttribute(s_gemm,    cudaFuncAttributeMaxDynamicSharedMemorySize, GEMM_SMEM);
    cudaFuncSetAttribute(pv_gemm,   cudaFuncAttributeMaxDynamicSharedMemorySize, GEMM_SMEM);

    const int M = BATCH * SEQ;                 // 8192
    dim3 blk(256);
    dim3 gblk(GTHREADS);

    dim3 gProj(HID / 128, M / 128, 3);
    proj_gemm<<<gProj, gblk, GEMM_SMEM>>>(qin, kin, vin, Wq, Wk, qp, kp, vp);

    dim3 gS(136, 1, BATCH);
    s_gemm<<<gS, gblk, GEMM_SMEM>>>(qp, kp, S);

    dim3 gSm(SEQ, BATCH);
    softmax_fast<<<gSm, blk>>>(S);

    dim3 gPV(HID / 128, SEQ / 128, BATCH);
    pv_gemm<<<gPV, gblk, GEMM_SMEM>>>(S, vp, out);
}